// round 1
// baseline (speedup 1.0000x reference)
#include <cuda_runtime.h>
#include <cstdint>

#define BI 128
#define BT 128
#define RR 36
#define WW 50
#define DD 256
#define ILAMB 20.0f     // 1/0.05
#define EPSV 1e-6f

#define IP 2            // imgs per block
#define JP 4            // caps per block
#define NPAIR 8         // IP*JP
#define KC 32           // K-chunk
#define NCHUNK (DD / KC)
#define MT 3            // 48 rows padded
#define NT 7            // 56 cols padded

// smem layout (floats)
#define A_PER_IMG (MT * 4 * 32 * 4)     // 1536
#define B_PER_CAP (NT * 4 * 32 * 2)     // 1792
#define STAGE_A_FLOATS (IP * A_PER_IMG) // 3072
#define KS_STRIDE (RR * 57)             // 2052 (57 pad: conflict-free col walks)
#define KS_FLOATS (NPAIR * KS_STRIDE)   // 16416
#define AL_OFF KS_FLOATS
#define BE_OFF (KS_FLOATS + NPAIR * RR)
#define SMEM_FLOATS (KS_FLOATS + NPAIR * RR + NPAIR * WW) // 17104
#define SMEM_BYTES (SMEM_FLOATS * 4)    // 68416

__device__ float g_nimgs[BI * RR * DD];
__device__ float g_ncaps[BT * WW * DD];

__device__ __forceinline__ unsigned f2tf32(float x) {
    unsigned r;
    asm("cvt.rna.tf32.f32 %0, %1;" : "=r"(r) : "f"(x));
    return r;
}

// ---------------------------------------------------------------------------
// Kernel 1: L2-normalize every row (imgs then caps), round to tf32, store.
// One warp per 256-wide row.
// ---------------------------------------------------------------------------
__global__ void norm_kernel(const float* __restrict__ imgs,
                            const float* __restrict__ caps) {
    int row  = blockIdx.x * 8 + (threadIdx.x >> 5);
    int lane = threadIdx.x & 31;
    const int n_img_rows = BI * RR;
    const int n_rows = n_img_rows + BT * WW;
    if (row >= n_rows) return;

    const float* src;
    float* dst;
    if (row < n_img_rows) {
        src = imgs + (size_t)row * DD;
        dst = g_nimgs + (size_t)row * DD;
    } else {
        int r2 = row - n_img_rows;
        src = caps + (size_t)r2 * DD;
        dst = g_ncaps + (size_t)r2 * DD;
    }
    const float4* s4 = reinterpret_cast<const float4*>(src);
    float4 v0 = s4[lane];
    float4 v1 = s4[lane + 32];
    float ss = v0.x * v0.x + v0.y * v0.y + v0.z * v0.z + v0.w * v0.w
             + v1.x * v1.x + v1.y * v1.y + v1.z * v1.z + v1.w * v1.w;
#pragma unroll
    for (int o = 16; o > 0; o >>= 1) ss += __shfl_xor_sync(0xffffffffu, ss, o);
    float inv = 1.0f / fmaxf(sqrtf(ss), 1e-8f);

    float4 o0, o1;
    o0.x = __uint_as_float(f2tf32(v0.x * inv));
    o0.y = __uint_as_float(f2tf32(v0.y * inv));
    o0.z = __uint_as_float(f2tf32(v0.z * inv));
    o0.w = __uint_as_float(f2tf32(v0.w * inv));
    o1.x = __uint_as_float(f2tf32(v1.x * inv));
    o1.y = __uint_as_float(f2tf32(v1.y * inv));
    o1.z = __uint_as_float(f2tf32(v1.z * inv));
    o1.w = __uint_as_float(f2tf32(v1.w * inv));
    float4* d4 = reinterpret_cast<float4*>(dst);
    d4[lane] = o0;
    d4[lane + 32] = o1;
}

// ---------------------------------------------------------------------------
// m16n8k8 tf32 mma
// ---------------------------------------------------------------------------
__device__ __forceinline__ void mma_tf32(float* c, const uint4& a, const uint2& b) {
    asm volatile(
        "mma.sync.aligned.m16n8k8.row.col.f32.tf32.tf32.f32 "
        "{%0,%1,%2,%3}, {%4,%5,%6,%7}, {%8,%9}, {%0,%1,%2,%3};\n"
        : "+f"(c[0]), "+f"(c[1]), "+f"(c[2]), "+f"(c[3])
        : "r"(a.x), "r"(a.y), "r"(a.z), "r"(a.w), "r"(b.x), "r"(b.y));
}

// ---------------------------------------------------------------------------
// Kernel 2: fused GEMM (tf32 mma.sync) + Sinkhorn + final contraction.
// Block = IP imgs x JP caps; warp w owns pair w (ii = w>>2, jj = w&3).
// ---------------------------------------------------------------------------
__global__ __launch_bounds__(256, 2)
void wass_kernel(const int* __restrict__ img_lens,
                 const int* __restrict__ cap_lens,
                 float* __restrict__ out) {
    extern __shared__ float smem[];
    const int i0 = blockIdx.y * IP;
    const int j0 = blockIdx.x * JP;
    const int tid = threadIdx.x;
    const int lane = tid & 31;
    const int wid = tid >> 5;

    float* As = smem;                   // [IP][MT][4][32][4] fragment-permuted
    float* Bs = smem + STAGE_A_FLOATS;  // [JP][NT][4][32][2] fragment-permuted

    float C[MT][NT][4];
#pragma unroll
    for (int mt = 0; mt < MT; ++mt)
#pragma unroll
        for (int nt = 0; nt < NT; ++nt)
#pragma unroll
            for (int c = 0; c < 4; ++c) C[mt][nt][c] = 0.0f;

    const int ii = wid >> 2;
    const int jj = wid & 3;
    const float4* Ap = reinterpret_cast<const float4*>(As) + ii * (MT * 4 * 32);
    const float2* Bp = reinterpret_cast<const float2*>(Bs) + jj * (NT * 4 * 32);

    for (int ch = 0; ch < NCHUNK; ++ch) {
        const int kc0 = ch * KC;
        __syncthreads();
        // ---- stage A (coalesced read, fragment-permuted write) ----
        for (int idx = tid; idx < IP * RR * KC; idx += 256) {
            int kk = idx & (KC - 1);
            int t = idx >> 5;
            int r = t % RR;
            int im = t / RR;
            float v = g_nimgs[((size_t)(i0 + im) * RR + r) * DD + kc0 + kk];
            int mt = r >> 4, rr = r & 15;
            int ks = kk >> 3, k8 = kk & 7;
            int ln = ((rr & 7) << 2) | (k8 & 3);
            int m = ((k8 >> 2) << 1) | (rr >> 3);
            As[((((im * MT + mt) * 4 + ks) * 32 + ln) << 2) + m] = v;
        }
        // ---- stage B ----
        for (int idx = tid; idx < JP * WW * KC; idx += 256) {
            int kk = idx & (KC - 1);
            int t = idx >> 5;
            int w = t % WW;
            int jc = t / WW;
            float v = g_ncaps[((size_t)(j0 + jc) * WW + w) * DD + kc0 + kk];
            int nt = w >> 3, n8 = w & 7;
            int ks = kk >> 3, k8 = kk & 7;
            int ln = (n8 << 2) | (k8 & 3);
            int m = k8 >> 2;
            Bs[((((jc * NT + nt) * 4 + ks) * 32 + ln) << 1) + m] = v;
        }
        __syncthreads();
        // ---- compute 4 k-steps ----
#pragma unroll
        for (int ks = 0; ks < 4; ++ks) {
            uint4 a[MT];
#pragma unroll
            for (int mt = 0; mt < MT; ++mt) {
                float4 av = Ap[(mt * 4 + ks) * 32 + lane];
                a[mt] = make_uint4(__float_as_uint(av.x), __float_as_uint(av.y),
                                   __float_as_uint(av.z), __float_as_uint(av.w));
            }
#pragma unroll
            for (int nt = 0; nt < NT; ++nt) {
                float2 bv = Bp[(nt * 4 + ks) * 32 + lane];
                uint2 b = make_uint2(__float_as_uint(bv.x), __float_as_uint(bv.y));
#pragma unroll
                for (int mt = 0; mt < MT; ++mt) mma_tf32(C[mt][nt], a[mt], b);
            }
        }
    }
    __syncthreads();  // staging region is reused as K below

    // ---------------- Sinkhorn (warp-private per pair) ----------------
    const int i = i0 + ii;
    const int j = j0 + jj;
    const int Ri = img_lens[i];
    const int Wj = cap_lens[j];
    float* Kp = smem + wid * KS_STRIDE;        // [36][57]
    float* alp = smem + AL_OFF + wid * RR;     // [36]
    float* bet = smem + BE_OFF + wid * WW;     // [50]

    const int gid = lane >> 2;
    const int tig = lane & 3;

    // K = exp((s-1)/lambda) masked; accumulate total sum
    float tsum = 0.0f;
#pragma unroll
    for (int mt = 0; mt < MT; ++mt)
#pragma unroll
        for (int nt = 0; nt < NT; ++nt)
#pragma unroll
            for (int c = 0; c < 4; ++c) {
                int r = mt * 16 + gid + ((c >> 1) << 3);
                int w = nt * 8 + (tig << 1) + (c & 1);
                if (r < Ri && w < Wj) {
                    float s = C[mt][nt][c];
                    float k = __expf(ILAMB * s - ILAMB);
                    Kp[r * 57 + w] = k;
                    tsum += k;
                }
            }
#pragma unroll
    for (int o = 16; o > 0; o >>= 1) tsum += __shfl_xor_sync(0xffffffffu, tsum, o);
    float alpha0 = 1.0f / (tsum + EPSV);

    for (int r = lane; r < Ri; r += 32) alp[r] = alpha0;
    for (int w = lane; w < Wj; w += 32) bet[w] = 1.0f;
    const float rm = 1.0f / (float)Ri;
    const float cm = 1.0f / (float)Wj;
    __syncwarp();

#pragma unroll
    for (int it = 0; it < 3; ++it) {
        for (int r = lane; r < Ri; r += 32) {
            float dot = 0.0f;
            for (int w = 0; w < Wj; ++w) dot += Kp[r * 57 + w] * bet[w];
            float a = alp[r];
            alp[r] = a * (rm / (a * dot + EPSV));
        }
        __syncwarp();
        for (int w = lane; w < Wj; w += 32) {
            float dot = 0.0f;
            for (int r = 0; r < Ri; ++r) dot += Kp[r * 57 + w] * alp[r];
            float b = bet[w];
            bet[w] = b * (cm / (b * dot + EPSV));
        }
        __syncwarp();
    }

    // final: sum s * K * alpha_r * beta_w over valid entries
    float acc = 0.0f;
#pragma unroll
    for (int mt = 0; mt < MT; ++mt)
#pragma unroll
        for (int nt = 0; nt < NT; ++nt)
#pragma unroll
            for (int c = 0; c < 4; ++c) {
                int r = mt * 16 + gid + ((c >> 1) << 3);
                int w = nt * 8 + (tig << 1) + (c & 1);
                if (r < Ri && w < Wj) {
                    float s = C[mt][nt][c];
                    float k = __expf(ILAMB * s - ILAMB);
                    acc += s * k * alp[r] * bet[w];
                }
            }
#pragma unroll
    for (int o = 16; o > 0; o >>= 1) acc += __shfl_xor_sync(0xffffffffu, acc, o);
    if (lane == 0) out[i * BT + j] = acc;
}

// ---------------------------------------------------------------------------
extern "C" void kernel_launch(void* const* d_in, const int* in_sizes, int n_in,
                              void* d_out, int out_size) {
    const float* imgs = (const float*)d_in[0];
    const float* caps = (const float*)d_in[1];
    const int* img_lens = (const int*)d_in[2];
    const int* cap_lens = (const int*)d_in[3];
    float* out = (float*)d_out;

    cudaFuncSetAttribute(wass_kernel,
                         cudaFuncAttributeMaxDynamicSharedMemorySize, SMEM_BYTES);

    // normalize: (128*36 + 128*50) rows, 8 rows per 256-thread block
    int n_rows = BI * RR + BT * WW;
    int nblk = (n_rows + 7) / 8;
    norm_kernel<<<nblk, 256>>>(imgs, caps);

    dim3 grid(BT / JP, BI / IP);  // (32, 64)
    wass_kernel<<<grid, 256, SMEM_BYTES>>>(img_lens, cap_lens, out);
}

// round 3
// speedup vs baseline: 1.9161x; 1.9161x over previous
#include <cuda_runtime.h>
#include <cstdint>

#define BI 128
#define BT 128
#define RR 36
#define WW 50
#define DD 256
#define ILAMB 20.0f     // 1/0.05
#define EPSV 1e-6f

#define IP 2            // imgs per block
#define JP 4            // caps per block
#define NPAIR 8         // IP*JP
#define KC 32           // K-chunk
#define NCHUNK (DD / KC)
#define MT 3            // 48 rows padded
#define NT 7            // 56 cols padded

#define STRIDE 36                    // KC + 4 pad -> stride%32==4: conflict-free frags
#define A_ROWS (IP * RR)             // 72 real rows staged
#define B_ROWS (JP * WW)             // 200 real rows staged
#define A_ROWS_PAD 48                // MT*16 (per image)
#define B_ROWS_PAD 56                // NT*8  (per cap)
#define A_FLOATS (IP * A_ROWS_PAD * STRIDE)   // 3456
#define B_FLOATS (JP * B_ROWS_PAD * STRIDE)   // 8064
#define BUF_FLOATS (A_FLOATS + B_FLOATS)      // 11520
#define BUF_BYTES (BUF_FLOATS * 4)            // 46080

// Sinkhorn scratch (reuses the two staging buffers after GEMM)
#define KS_STRIDE (RR * 57)             // 2052
#define KS_FLOATS (NPAIR * KS_STRIDE)   // 16416
#define AL_OFF KS_FLOATS
#define BE_OFF (KS_FLOATS + NPAIR * RR)
#define SINK_FLOATS (KS_FLOATS + NPAIR * RR + NPAIR * WW)  // 17104

#define SMEM_FLOATS (2 * BUF_FLOATS)    // 23040 > 17104
#define SMEM_BYTES (SMEM_FLOATS * 4)    // 92160

__device__ float g_nimgs[BI * RR * DD];
__device__ float g_ncaps[BT * WW * DD];

__device__ __forceinline__ unsigned f2tf32(float x) {
    unsigned r;
    asm("cvt.rna.tf32.f32 %0, %1;" : "=r"(r) : "f"(x));
    return r;
}

__device__ __forceinline__ void cp16(uint32_t dst, const float* src) {
    asm volatile("cp.async.cg.shared.global [%0], [%1], 16;\n"
                 :: "r"(dst), "l"(src));
}

// ---------------------------------------------------------------------------
// Kernel 1: L2-normalize every row (imgs then caps), round to tf32, store.
// ---------------------------------------------------------------------------
__global__ void norm_kernel(const float* __restrict__ imgs,
                            const float* __restrict__ caps) {
    int row  = blockIdx.x * 8 + (threadIdx.x >> 5);
    int lane = threadIdx.x & 31;
    const int n_img_rows = BI * RR;
    const int n_rows = n_img_rows + BT * WW;
    if (row >= n_rows) return;

    const float* src;
    float* dst;
    if (row < n_img_rows) {
        src = imgs + (size_t)row * DD;
        dst = g_nimgs + (size_t)row * DD;
    } else {
        int r2 = row - n_img_rows;
        src = caps + (size_t)r2 * DD;
        dst = g_ncaps + (size_t)r2 * DD;
    }
    const float4* s4 = reinterpret_cast<const float4*>(src);
    float4 v0 = s4[lane];
    float4 v1 = s4[lane + 32];
    float ss = v0.x * v0.x + v0.y * v0.y + v0.z * v0.z + v0.w * v0.w
             + v1.x * v1.x + v1.y * v1.y + v1.z * v1.z + v1.w * v1.w;
#pragma unroll
    for (int o = 16; o > 0; o >>= 1) ss += __shfl_xor_sync(0xffffffffu, ss, o);
    float inv = 1.0f / fmaxf(sqrtf(ss), 1e-8f);

    float4 o0, o1;
    o0.x = __uint_as_float(f2tf32(v0.x * inv));
    o0.y = __uint_as_float(f2tf32(v0.y * inv));
    o0.z = __uint_as_float(f2tf32(v0.z * inv));
    o0.w = __uint_as_float(f2tf32(v0.w * inv));
    o1.x = __uint_as_float(f2tf32(v1.x * inv));
    o1.y = __uint_as_float(f2tf32(v1.y * inv));
    o1.z = __uint_as_float(f2tf32(v1.z * inv));
    o1.w = __uint_as_float(f2tf32(v1.w * inv));
    float4* d4 = reinterpret_cast<float4*>(dst);
    d4[lane] = o0;
    d4[lane + 32] = o1;
}

// ---------------------------------------------------------------------------
// m16n8k8 tf32 mma
// ---------------------------------------------------------------------------
__device__ __forceinline__ void mma_tf32(float* c, const uint4& a, const uint2& b) {
    asm volatile(
        "mma.sync.aligned.m16n8k8.row.col.f32.tf32.tf32.f32 "
        "{%0,%1,%2,%3}, {%4,%5,%6,%7}, {%8,%9}, {%0,%1,%2,%3};\n"
        : "+f"(c[0]), "+f"(c[1]), "+f"(c[2]), "+f"(c[3])
        : "r"(a.x), "r"(a.y), "r"(a.z), "r"(a.w), "r"(b.x), "r"(b.y));
}

// Stage one K-chunk (A: 72 real rows, B: 200 real rows) via cp.async into a
// linear [row][k] layout, stride 36 floats, rows padded per image/cap.
__device__ __forceinline__ void stage_chunk(uint32_t sbase, int i0, int j0,
                                            int kc0, int tid) {
#pragma unroll
    for (int s = 0; s < 3; ++s) {
        int idx = tid + 256 * s;
        if (idx < A_ROWS * 8) {
            int row = idx >> 3, q = idx & 7;
            int im = (row >= RR) ? 1 : 0;
            int r = row - im * RR;
            const float* src = g_nimgs + ((size_t)(i0 + im) * RR + r) * DD + kc0 + q * 4;
            cp16(sbase + (im * A_ROWS_PAD + r) * (STRIDE * 4) + q * 16, src);
        }
    }
    uint32_t bbase = sbase + A_FLOATS * 4;
#pragma unroll
    for (int s = 0; s < 7; ++s) {
        int idx = tid + 256 * s;
        if (idx < B_ROWS * 8) {
            int row = idx >> 3, q = idx & 7;
            int jc = row / WW;        // const-div -> mul/shift
            int w = row - jc * WW;
            const float* src = g_ncaps + ((size_t)(j0 + jc) * WW + w) * DD + kc0 + q * 4;
            cp16(bbase + (jc * B_ROWS_PAD + w) * (STRIDE * 4) + q * 16, src);
        }
    }
}

// ---------------------------------------------------------------------------
// Kernel 2: fused GEMM (tf32 mma.sync, cp.async double-buffered) + Sinkhorn.
// Block = IP imgs x JP caps; warp w owns pair w (ii = w>>2, jj = w&3).
// ---------------------------------------------------------------------------
__global__ __launch_bounds__(256, 2)
void wass_kernel(const int* __restrict__ img_lens,
                 const int* __restrict__ cap_lens,
                 float* __restrict__ out) {
    extern __shared__ float smem[];
    const int i0 = blockIdx.y * IP;
    const int j0 = blockIdx.x * JP;
    const int tid = threadIdx.x;
    const int lane = tid & 31;
    const int wid = tid >> 5;
    const int gid = lane >> 2;
    const int tig = lane & 3;
    const int ii = wid >> 2;
    const int jj = wid & 3;

    uint32_t sb;
    asm("{ .reg .u64 t; cvta.to.shared.u64 t, %1; cvt.u32.u64 %0, t; }"
        : "=r"(sb) : "l"(smem));

    float C[MT][NT][4];
#pragma unroll
    for (int mt = 0; mt < MT; ++mt)
#pragma unroll
        for (int nt = 0; nt < NT; ++nt)
#pragma unroll
            for (int c = 0; c < 4; ++c) C[mt][nt][c] = 0.0f;

    // prologue: stage chunk 0 into buffer 0
    stage_chunk(sb, i0, j0, 0, tid);
    asm volatile("cp.async.commit_group;" ::: "memory");

    for (int ch = 0; ch < NCHUNK; ++ch) {
        if (ch + 1 < NCHUNK) {
            stage_chunk(sb + ((ch + 1) & 1) * BUF_BYTES, i0, j0, (ch + 1) * KC, tid);
            asm volatile("cp.async.commit_group;" ::: "memory");
            asm volatile("cp.async.wait_group 1;" ::: "memory");
        } else {
            asm volatile("cp.async.wait_group 0;" ::: "memory");
        }
        __syncthreads();

        const float* Abuf = smem + (ch & 1) * BUF_FLOATS + ii * (A_ROWS_PAD * STRIDE);
        const float* Bbuf = smem + (ch & 1) * BUF_FLOATS + A_FLOATS
                          + jj * (B_ROWS_PAD * STRIDE);
#pragma unroll
        for (int ks = 0; ks < 4; ++ks) {
            uint4 a[MT];
#pragma unroll
            for (int mt = 0; mt < MT; ++mt) {
                const float* p = Abuf + (mt * 16 + gid) * STRIDE + ks * 8 + tig;
                a[mt].x = __float_as_uint(p[0]);
                a[mt].y = __float_as_uint(p[8 * STRIDE]);
                a[mt].z = __float_as_uint(p[4]);
                a[mt].w = __float_as_uint(p[8 * STRIDE + 4]);
            }
#pragma unroll
            for (int nt = 0; nt < NT; ++nt) {
                const float* q = Bbuf + (nt * 8 + gid) * STRIDE + ks * 8 + tig;
                uint2 b;
                b.x = __float_as_uint(q[0]);
                b.y = __float_as_uint(q[4]);
#pragma unroll
                for (int mt = 0; mt < MT; ++mt) mma_tf32(C[mt][nt], a[mt], b);
            }
        }
        __syncthreads();   // buffer (ch&1) free for restage / Sinkhorn reuse
    }

    // ---------------- Sinkhorn (warp-private per pair) ----------------
    const int i = i0 + ii;
    const int j = j0 + jj;
    const int Ri = img_lens[i];
    const int Wj = cap_lens[j];
    float* Kp = smem + wid * KS_STRIDE;        // [36][57]
    float* alp = smem + AL_OFF + wid * RR;     // [36]
    float* bet = smem + BE_OFF + wid * WW;     // [50]

    // K = exp((s-1)/lambda) masked; accumulate total sum
    float tsum = 0.0f;
#pragma unroll
    for (int mt = 0; mt < MT; ++mt)
#pragma unroll
        for (int nt = 0; nt < NT; ++nt)
#pragma unroll
            for (int c = 0; c < 4; ++c) {
                int r = mt * 16 + gid + ((c >> 1) << 3);
                int w = nt * 8 + (tig << 1) + (c & 1);
                if (r < Ri && w < Wj) {
                    float s = C[mt][nt][c];
                    float k = __expf(ILAMB * s - ILAMB);
                    Kp[r * 57 + w] = k;
                    tsum += k;
                }
            }
#pragma unroll
    for (int o = 16; o > 0; o >>= 1) tsum += __shfl_xor_sync(0xffffffffu, tsum, o);
    float alpha0 = 1.0f / (tsum + EPSV);

    for (int r = lane; r < Ri; r += 32) alp[r] = alpha0;
    for (int w = lane; w < Wj; w += 32) bet[w] = 1.0f;
    const float rm = 1.0f / (float)Ri;
    const float cm = 1.0f / (float)Wj;
    __syncwarp();

#pragma unroll
    for (int it = 0; it < 3; ++it) {
        for (int r = lane; r < Ri; r += 32) {
            float dot = 0.0f;
            for (int w = 0; w < Wj; ++w) dot += Kp[r * 57 + w] * bet[w];
            float a = alp[r];
            alp[r] = a * (rm / (a * dot + EPSV));
        }
        __syncwarp();
        for (int w = lane; w < Wj; w += 32) {
            float dot = 0.0f;
            for (int r = 0; r < Ri; ++r) dot += Kp[r * 57 + w] * alp[r];
            float b = bet[w];
            bet[w] = b * (cm / (b * dot + EPSV));
        }
        __syncwarp();
    }

    // final: sum s * K * alpha_r * beta_w over valid entries
    float acc = 0.0f;
#pragma unroll
    for (int mt = 0; mt < MT; ++mt)
#pragma unroll
        for (int nt = 0; nt < NT; ++nt)
#pragma unroll
            for (int c = 0; c < 4; ++c) {
                int r = mt * 16 + gid + ((c >> 1) << 3);
                int w = nt * 8 + (tig << 1) + (c & 1);
                if (r < Ri && w < Wj) {
                    float s = C[mt][nt][c];
                    float k = __expf(ILAMB * s - ILAMB);
                    acc += s * k * alp[r] * bet[w];
                }
            }
#pragma unroll
    for (int o = 16; o > 0; o >>= 1) acc += __shfl_xor_sync(0xffffffffu, acc, o);
    if (lane == 0) out[i * BT + j] = acc;
}

// ---------------------------------------------------------------------------
extern "C" void kernel_launch(void* const* d_in, const int* in_sizes, int n_in,
                              void* d_out, int out_size) {
    const float* imgs = (const float*)d_in[0];
    const float* caps = (const float*)d_in[1];
    const int* img_lens = (const int*)d_in[2];
    const int* cap_lens = (const int*)d_in[3];
    float* out = (float*)d_out;

    cudaFuncSetAttribute(wass_kernel,
                         cudaFuncAttributeMaxDynamicSharedMemorySize, SMEM_BYTES);

    int n_rows = BI * RR + BT * WW;
    int nblk = (n_rows + 7) / 8;
    norm_kernel<<<nblk, 256>>>(imgs, caps);

    dim3 grid(BT / JP, BI / IP);  // (32, 64)
    wass_kernel<<<grid, 256, SMEM_BYTES>>>(img_lens, cap_lens, out);
}